// round 6
// baseline (speedup 1.0000x reference)
#include <cuda_runtime.h>
#include <cstdint>

#define T_SEQ 128
#define BATCH 512
#define DIM   128
#define NQ    8
#define NCH   32   // 4 gates * 8 wires

typedef unsigned long long u64;

// Scratch: zpre[(t*BATCH+b)*32 + ch] = x_t[b] @ Wx[:,ch], ch = gate*8+wire
__device__ float g_zpre[(size_t)T_SEQ * BATCH * NCH];
// dump target for lanes that don't own an output slot (never read)
__device__ float g_dump[64];

__device__ __forceinline__ float tanh_approx(float x) {
    float r;
    asm("tanh.approx.f32 %0, %1;" : "=f"(r) : "f"(x));
    return r;
}
__device__ __forceinline__ void ffma2(u64& acc, u64 a, u64 b) {
    asm("fma.rn.f32x2 %0, %1, %2, %0;" : "+l"(acc) : "l"(a), "l"(b));
}
__device__ __forceinline__ u64 pack2(float lo, float hi) {
    u64 r; asm("mov.b64 %0, {%1, %2};" : "=l"(r) : "f"(lo), "f"(hi)); return r;
}
__device__ __forceinline__ void unpack2(float& lo, float& hi, u64 v) {
    asm("mov.b64 {%0, %1}, %2;" : "=f"(lo), "=f"(hi) : "l"(v));
}

// ---------------------------------------------------------------------------
// Kernel A: zpre = X @ Wx.  X: (T*B,128), Wx: (128,32) from x-rows of W*.
// Row-pair FFMA2: thread owns rows (2l, 2l+1); LDS.64 gives the packed x pair
// directly (no pack MOVs); weights pre-duplicated in smem as (w,w) u64.
// Block: 128 threads = 64 rows x 32 cols (warp w owns cols 8w..8w+7).
// ---------------------------------------------------------------------------
__global__ void __launch_bounds__(128) qlstm_gemm(
    const float* __restrict__ x,
    const float* __restrict__ Wf, const float* __restrict__ Wi,
    const float* __restrict__ Wu, const float* __restrict__ Wo)
{
    __shared__ __align__(16) u64   wdup[128][32];  // (w,w) per [k][col]; 32 KB
    __shared__ __align__(16) float xs[32][66];     // [k_in_chunk][row], 8-aligned rows

    const int tid  = threadIdx.x;
    const int row0 = blockIdx.x * 64;

    // Stage duplicated weights (one-time)
    #pragma unroll 4
    for (int i = tid; i < 128 * 32; i += 128) {
        int k = i >> 5, j = i & 31;
        int g = j >> 3, w = j & 7;
        const float* Wg = (g == 0) ? Wf : (g == 1) ? Wi : (g == 2) ? Wu : Wo;
        float v = Wg[k * 8 + w];
        wdup[k][j] = pack2(v, v);
    }

    const int lane = tid & 31;
    const int c0   = (tid >> 5) * 8;   // warp-uniform col group

    u64 acc[8];
    #pragma unroll
    for (int q = 0; q < 8; ++q) acc[q] = 0ull;

    for (int kc = 0; kc < 4; ++kc) {
        __syncthreads();
        // stage 64 rows x 32 k: warp reads one row's 32 consecutive floats
        #pragma unroll 4
        for (int i = tid; i < 64 * 32; i += 128) {
            int r = i >> 5, kk = i & 31;
            xs[kk][r] = x[(size_t)(row0 + r) * DIM + kc * 32 + kk];
        }
        __syncthreads();

        #pragma unroll
        for (int k = 0; k < 32; ++k) {
            u64 xp = *reinterpret_cast<const u64*>(&xs[k][2 * lane]);
            const ulonglong2* wk =
                reinterpret_cast<const ulonglong2*>(&wdup[kc * 32 + k][c0]);
            ulonglong2 wa = wk[0];
            ulonglong2 wb = wk[1];
            ffma2(acc[0], xp, wa.x); ffma2(acc[1], xp, wa.y);
            ffma2(acc[2], xp, wb.x); ffma2(acc[3], xp, wb.y);
            const ulonglong2* wk2 = wk + 2;
            ulonglong2 wc = wk2[0];
            ulonglong2 wd = wk2[1];
            ffma2(acc[4], xp, wc.x); ffma2(acc[5], xp, wc.y);
            ffma2(acc[6], xp, wd.x); ffma2(acc[7], xp, wd.y);
        }
    }

    // Epilogue: acc[q] = (row 2l, row 2l+1) for col c0+q
    float lo[8], hi[8];
    #pragma unroll
    for (int q = 0; q < 8; ++q) unpack2(lo[q], hi[q], acc[q]);

    size_t ra = (size_t)(row0 + 2 * lane) * NCH + c0;
    float4* d0 = reinterpret_cast<float4*>(g_zpre + ra);
    d0[0] = make_float4(lo[0], lo[1], lo[2], lo[3]);
    d0[1] = make_float4(lo[4], lo[5], lo[6], lo[7]);
    float4* d1 = reinterpret_cast<float4*>(g_zpre + ra + NCH);
    d1[0] = make_float4(hi[0], hi[1], hi[2], hi[3]);
    d1[1] = make_float4(hi[4], hi[5], hi[6], hi[7]);
}

// ---------------------------------------------------------------------------
// Kernel B: recurrence, 4 independent batch rows interleaved per warp.
// lane = gate*8 + wire (same for all 4 rows). The 4 rows' chains interleave in
// the instruction stream so fixed-lat / SHFL / MUFU stalls are filled.
// Quantum layer (analytic): <Z_w> = prod_{k<=w} cos(phi_k) (w>=1),
//                           <Z_0> = prod_{k=1..7} cos(phi_k).
// ---------------------------------------------------------------------------
#define R4C 4
__global__ void __launch_bounds__(32) qlstm_recurrent(
    const float* __restrict__ Wf, const float* __restrict__ bf, const float* __restrict__ thf,
    const float* __restrict__ Wi, const float* __restrict__ bi, const float* __restrict__ thi,
    const float* __restrict__ Wu, const float* __restrict__ bu, const float* __restrict__ thu,
    const float* __restrict__ Wo, const float* __restrict__ bo, const float* __restrict__ tho,
    float* __restrict__ out)
{
    const int lane = threadIdx.x & 31;
    const int row0 = blockIdx.x * R4C;            // rows row0..row0+3
    const int gate = lane >> 3;
    const int wire = lane & 7;
    const int base = lane & 24;                    // gate*8

    const float* Wg = (gate == 0) ? Wf : (gate == 1) ? Wi : (gate == 2) ? Wu : Wo;
    const float* bg = (gate == 0) ? bf : (gate == 1) ? bi : (gate == 2) ? bu : bo;
    const float* tg = (gate == 0) ? thf : (gate == 1) ? thi : (gate == 2) ? thu : tho;

    float wh[8];
    #pragma unroll
    for (int k = 0; k < 8; ++k) wh[k] = Wg[(DIM + k) * NQ + wire];

    const float cbias = bg[wire] + tg[wire];
    const bool  isU   = (gate == 2);
    const float aScl  = isU ? 1.0f : 0.5f;
    const float aMul  = isU ? 1.0f : 0.5f;
    const float aAdd  = isU ? 0.0f : 0.5f;

    const bool w0z = (wire == 0);
    const bool q1  = (wire >= 1);
    const bool q2  = (wire >= 2);
    const bool q4  = (wire >= 4);

    // per-row state
    float hw[R4C], cs[R4C], zn0[R4C], zn1[R4C];
    const float* zp[R4C];
    float* st[R4C];
    #pragma unroll
    for (int j = 0; j < R4C; ++j) {
        hw[j] = 0.0f; cs[j] = 0.0f;
        zp[j] = g_zpre + (size_t)(row0 + j) * NCH + lane;
        st[j] = (lane < 8) ? (out + (size_t)(row0 + j) * NQ + wire)
                           : (g_dump + lane);
    }
    const size_t sstr = (lane < 8) ? (size_t)(BATCH * NQ) : 0;
    const size_t tstride = (size_t)BATCH * NCH;

    #pragma unroll
    for (int j = 0; j < R4C; ++j) {
        zn0[j] = zp[j][0];
        zn1[j] = zp[j][tstride];
    }

    const unsigned FULL = 0xffffffffu;

    #pragma unroll 1
    for (int t = 0; t < T_SEQ; ++t) {
        int t2 = (t + 2 < T_SEQ) ? (t + 2) : (T_SEQ - 1);

        float z[R4C];
        #pragma unroll
        for (int j = 0; j < R4C; ++j) {
            z[j] = zn0[j] + cbias;
            zn0[j] = zn1[j];
            zn1[j] = zp[j][(size_t)t2 * tstride];     // prefetch, off-chain
        }

        // z += h . wh  (h allgathered from per-wire copies; serial FMA ok —
        // stalls filled by the other rows)
        #pragma unroll
        for (int k = 0; k < 8; ++k) {
            float hk[R4C];
            #pragma unroll
            for (int j = 0; j < R4C; ++j) hk[j] = __shfl_sync(FULL, hw[j], base + k);
            #pragma unroll
            for (int j = 0; j < R4C; ++j) z[j] = fmaf(hk[j], wh[k], z[j]);
        }

        float c[R4C], p[R4C];
        #pragma unroll
        for (int j = 0; j < R4C; ++j) {
            c[j] = __cosf(z[j]);
            p[j] = w0z ? 1.0f : c[j];    // lane0 contributes 1 to the scan
        }

        // masked Kogge-Stone segmented scan (width 8): p = prod_{k=1..wire} c_k
        #pragma unroll
        for (int j = 0; j < R4C; ++j) {
            float u = __shfl_up_sync(FULL, p[j], 1, 8);
            p[j] *= q1 ? u : 1.0f;
        }
        #pragma unroll
        for (int j = 0; j < R4C; ++j) {
            float u = __shfl_up_sync(FULL, p[j], 2, 8);
            p[j] *= q2 ? u : 1.0f;
        }
        #pragma unroll
        for (int j = 0; j < R4C; ++j) {
            float u = __shfl_up_sync(FULL, p[j], 4, 8);
            p[j] *= q4 ? u : 1.0f;
        }

        float act[R4C];
        #pragma unroll
        for (int j = 0; j < R4C; ++j) {
            float c0s = __shfl_sync(FULL, c[j], base);      // c_0 of segment
            float p7  = __shfl_sync(FULL, p[j], base + 7);  // prod c1..c7
            float e   = w0z ? p7 : c0s * p[j];              // <Z_wire>
            act[j] = fmaf(aMul, tanh_approx(e * aScl), aAdd);
        }

        #pragma unroll
        for (int j = 0; j < R4C; ++j) {
            float fv = __shfl_sync(FULL, act[j], wire);
            float iv = __shfl_sync(FULL, act[j], wire + 8);
            float gv = __shfl_sync(FULL, act[j], wire + 16);
            float ov = __shfl_sync(FULL, act[j], wire + 24);
            cs[j] = fmaf(fv, cs[j], iv * gv);
            hw[j] = ov * tanh_approx(cs[j]);
        }

        #pragma unroll
        for (int j = 0; j < R4C; ++j) {
            *st[j] = hw[j];        // branch-free; non-owner lanes hit g_dump
            st[j] += sstr;
        }
    }

    if (lane < 8) {
        const size_t outs_sz = (size_t)T_SEQ * BATCH * NQ;
        #pragma unroll
        for (int j = 0; j < R4C; ++j) {
            out[outs_sz + (size_t)(row0 + j) * NQ + wire] = hw[j];   // final hx
            out[outs_sz + (size_t)BATCH * NQ
                        + (size_t)(row0 + j) * NQ + wire] = cs[j];   // final cx
        }
    }
}

// ---------------------------------------------------------------------------
// Launch
// ---------------------------------------------------------------------------
extern "C" void kernel_launch(void* const* d_in, const int* in_sizes, int n_in,
                              void* d_out, int out_size)
{
    const float* x   = (const float*)d_in[0];
    const float* Wf  = (const float*)d_in[1];
    const float* bf  = (const float*)d_in[2];
    const float* thf = (const float*)d_in[3];
    const float* Wi  = (const float*)d_in[4];
    const float* bi  = (const float*)d_in[5];
    const float* thi = (const float*)d_in[6];
    const float* Wu  = (const float*)d_in[7];
    const float* bu  = (const float*)d_in[8];
    const float* thu = (const float*)d_in[9];
    const float* Wo  = (const float*)d_in[10];
    const float* bo  = (const float*)d_in[11];
    const float* tho = (const float*)d_in[12];
    float* out = (float*)d_out;

    qlstm_gemm<<<(T_SEQ * BATCH) / 64, 128>>>(x, Wf, Wi, Wu, Wo);
    qlstm_recurrent<<<BATCH / R4C, 32>>>(Wf, bf, thf, Wi, bi, thi,
                                         Wu, bu, thu, Wo, bo, tho, out);
}

// round 7
// speedup vs baseline: 1.9748x; 1.9748x over previous
#include <cuda_runtime.h>
#include <cstdint>

#define T_SEQ 128
#define BATCH 512
#define DIM   128
#define NQ    8
#define NCH   32   // 4 gates * 8 wires

typedef unsigned long long u64;

// Scratch: zpre[(t*BATCH+b)*32 + ch] = x_t[b] @ Wx[:,ch], ch = gate*8+wire
__device__ float g_zpre[(size_t)T_SEQ * BATCH * NCH];
// dump target for lanes that don't own an output slot (never read)
__device__ float g_dump[64];

__device__ __forceinline__ float tanh_approx(float x) {
    float r;
    asm("tanh.approx.f32 %0, %1;" : "=f"(r) : "f"(x));
    return r;
}
__device__ __forceinline__ void ffma2(u64& acc, u64 a, u64 b) {
    asm("fma.rn.f32x2 %0, %1, %2, %0;" : "+l"(acc) : "l"(a), "l"(b));
}
__device__ __forceinline__ u64 pack2(float lo, float hi) {
    u64 r; asm("mov.b64 %0, {%1, %2};" : "=l"(r) : "f"(lo), "f"(hi)); return r;
}

// ---------------------------------------------------------------------------
// Kernel A (R3 version, verbatim): zpre = X @ Wx via packed f32x2 FMA.
// ---------------------------------------------------------------------------
__global__ void __launch_bounds__(128) qlstm_gemm(
    const float* __restrict__ x,
    const float* __restrict__ Wf, const float* __restrict__ Wi,
    const float* __restrict__ Wu, const float* __restrict__ Wo)
{
    __shared__ __align__(16) float ws[128][32];
    __shared__ float xs[32][129];
    const int tid  = threadIdx.x;
    const int row0 = blockIdx.x * 128;

    #pragma unroll 4
    for (int i = tid; i < 128 * 32; i += 128) {
        int k = i >> 5, j = i & 31;
        int g = j >> 3, w = j & 7;
        const float* Wg = (g == 0) ? Wf : (g == 1) ? Wi : (g == 2) ? Wu : Wo;
        ws[k][j] = Wg[k * 8 + w];
    }

    const int lane = tid & 31;
    const int c0   = (tid >> 5) * 8;

    u64 acc[4][4];
    #pragma unroll
    for (int r = 0; r < 4; r++)
        #pragma unroll
        for (int q = 0; q < 4; q++) acc[r][q] = 0ull;

    for (int kc = 0; kc < 4; ++kc) {
        __syncthreads();
        #pragma unroll 4
        for (int i = tid; i < 128 * 32; i += 128) {
            int r = i >> 5, kk = i & 31;
            xs[kk][r] = x[(size_t)(row0 + r) * DIM + kc * 32 + kk];
        }
        __syncthreads();

        #pragma unroll
        for (int k = 0; k < 32; ++k) {
            float xv0 = xs[k][lane      ];
            float xv1 = xs[k][lane + 32 ];
            float xv2 = xs[k][lane + 64 ];
            float xv3 = xs[k][lane + 96 ];
            u64 xx0 = pack2(xv0, xv0);
            u64 xx1 = pack2(xv1, xv1);
            u64 xx2 = pack2(xv2, xv2);
            u64 xx3 = pack2(xv3, xv3);
            const u64* wk = reinterpret_cast<const u64*>(&ws[kc * 32 + k][c0]);
            u64 w0 = wk[0], w1 = wk[1], w2 = wk[2], w3 = wk[3];
            ffma2(acc[0][0], xx0, w0); ffma2(acc[0][1], xx0, w1);
            ffma2(acc[0][2], xx0, w2); ffma2(acc[0][3], xx0, w3);
            ffma2(acc[1][0], xx1, w0); ffma2(acc[1][1], xx1, w1);
            ffma2(acc[1][2], xx1, w2); ffma2(acc[1][3], xx1, w3);
            ffma2(acc[2][0], xx2, w0); ffma2(acc[2][1], xx2, w1);
            ffma2(acc[2][2], xx2, w2); ffma2(acc[2][3], xx2, w3);
            ffma2(acc[3][0], xx3, w0); ffma2(acc[3][1], xx3, w1);
            ffma2(acc[3][2], xx3, w2); ffma2(acc[3][3], xx3, w3);
        }
    }

    #pragma unroll
    for (int rr = 0; rr < 4; ++rr) {
        int r = row0 + lane + 32 * rr;
        u64* dst = reinterpret_cast<u64*>(g_zpre + (size_t)r * NCH + c0);
        dst[0] = acc[rr][0]; dst[1] = acc[rr][1];
        dst[2] = acc[rr][2]; dst[3] = acc[rr][3];
    }
}

// ---------------------------------------------------------------------------
// Kernel B: recurrence, one warp per row, cross-lane traffic via per-warp
// shared-memory exchanges (SHFL measured ~30 cyc serialized solo; LDS
// pipelines at floor 2).  lane = gate*8 + wire.
// <Z_w> = prod_{k<=w} cos(phi_k) (w>=1), <Z_0> = prod_{k=1..7} cos(phi_k).
// ---------------------------------------------------------------------------
__global__ void __launch_bounds__(128) qlstm_recurrent(
    const float* __restrict__ Wf, const float* __restrict__ bf, const float* __restrict__ thf,
    const float* __restrict__ Wi, const float* __restrict__ bi, const float* __restrict__ thi,
    const float* __restrict__ Wu, const float* __restrict__ bu, const float* __restrict__ thu,
    const float* __restrict__ Wo, const float* __restrict__ bo, const float* __restrict__ tho,
    float* __restrict__ out)
{
    __shared__ __align__(16) float cbuf[4][32];
    __shared__ __align__(16) float abuf[4][32];   // [wire*4 + gate]
    __shared__ __align__(16) float hbuf[4][32];

    const int lane = threadIdx.x & 31;
    const int warp = threadIdx.x >> 5;
    const int row  = blockIdx.x * 4 + warp;       // 0..511
    const int gate = lane >> 3;
    const int wire = lane & 7;
    const int base = lane & 24;                    // gate*8

    const float* Wg = (gate == 0) ? Wf : (gate == 1) ? Wi : (gate == 2) ? Wu : Wo;
    const float* bg = (gate == 0) ? bf : (gate == 1) ? bi : (gate == 2) ? bu : bo;
    const float* tg = (gate == 0) ? thf : (gate == 1) ? thi : (gate == 2) ? thu : tho;

    float wh0 = Wg[(DIM + 0) * NQ + wire];
    float wh1 = Wg[(DIM + 1) * NQ + wire];
    float wh2 = Wg[(DIM + 2) * NQ + wire];
    float wh3 = Wg[(DIM + 3) * NQ + wire];
    float wh4 = Wg[(DIM + 4) * NQ + wire];
    float wh5 = Wg[(DIM + 5) * NQ + wire];
    float wh6 = Wg[(DIM + 6) * NQ + wire];
    float wh7 = Wg[(DIM + 7) * NQ + wire];

    const float cbias = bg[wire] + tg[wire];
    const bool  isU   = (gate == 2);
    const float aScl  = isU ? 1.0f : 0.5f;
    const float aMul  = isU ? 1.0f : 0.5f;
    const float aAdd  = isU ? 0.0f : 0.5f;

    const bool p0 = (wire & 1) != 0;
    const bool p1 = (wire & 2) != 0;
    const bool p2 = (wire & 4) != 0;

    float h0=0,h1=0,h2=0,h3=0,h4=0,h5=0,h6=0,h7=0;
    float cstate = 0.0f;

    // branch-free output pointer
    float* st = (lane < 8) ? (out + (size_t)row * NQ + wire) : (g_dump + lane);
    const size_t sstr = (lane < 8) ? (size_t)(BATCH * NQ) : 0;

    const float* zp = g_zpre + (size_t)row * NCH + lane;
    const size_t tstride = (size_t)BATCH * NCH;
    float zn0 = zp[0];
    float zn1 = zp[tstride];

    const float4* cseg = reinterpret_cast<const float4*>(&cbuf[warp][base]);
    const float4* hseg = reinterpret_cast<const float4*>(&hbuf[warp][base]);
    const float4* aseg = reinterpret_cast<const float4*>(&abuf[warp][wire * 4]);

    #pragma unroll 1
    for (int t = 0; t < T_SEQ; ++t) {
        float zb = zn0 + cbias;
        zn0 = zn1;
        int t2 = (t + 2 < T_SEQ) ? (t + 2) : (T_SEQ - 1);
        zn1 = zp[(size_t)t2 * tstride];             // off-chain prefetch

        // z = zb + h . wh  (mul/add tree)
        float m0 = h0*wh0, m1 = h1*wh1, m2 = h2*wh2, m3 = h3*wh3;
        float m4 = h4*wh4, m5 = h5*wh5, m6 = h6*wh6, m7 = h7*wh7;
        float a01 = m0+m1, a23 = m2+m3, a45 = m4+m5, a67 = m6+m7;
        float z = ((a01+a23) + (a45+a67)) + zb;

        float c = __cosf(z);

        // --- exchange 1: segment cosines via smem ---
        cbuf[warp][lane] = c;
        __syncwarp();
        float4 A = cseg[0];
        float4 B = cseg[1];
        float cc0 = A.x, cc1 = A.y, cc2 = A.z, cc3 = A.w;
        float cc4 = B.x, cc5 = B.y, cc6 = B.z, cc7 = B.w;

        // prefix products
        float m01 = cc0*cc1, m23 = cc2*cc3, m45 = cc4*cc5, m67 = cc6*cc7;
        float m0123 = m01*m23, m4567 = m45*m67;
        float P1 = m01;
        float P2 = m01*cc2;
        float P3 = m0123;
        float P4 = m0123*cc4;
        float P5 = m0123*m45;
        float P6 = m0123*(m45*cc6);
        float P7 = m0123*m4567;
        float E0 = (cc1*m23)*m4567;          // prod c1..c7

        // mux by wire bits
        float t0v = p0 ? P1 : E0;
        float t1v = p0 ? P3 : P2;
        float t2v = p0 ? P5 : P4;
        float t3v = p0 ? P7 : P6;
        float u0 = p1 ? t1v : t0v;
        float u1 = p1 ? t3v : t2v;
        float e  = p2 ? u1 : u0;             // <Z_wire>

        float act = fmaf(aMul, tanh_approx(e * aScl), aAdd);

        // --- exchange 2: gate values, transposed so one LDS.128 gathers ---
        abuf[warp][wire * 4 + gate] = act;
        __syncwarp();
        float4 G = aseg[0];                   // (f, i, g, o) for this wire

        cstate   = fmaf(G.x, cstate, G.y * G.z);
        float hw = G.w * tanh_approx(cstate);

        *st = hw;                             // branch-free store
        st += sstr;

        // --- exchange 3: new hidden state ---
        hbuf[warp][lane] = hw;                // identical across segments per wire
        __syncwarp();
        float4 H0 = hseg[0];
        float4 H1 = hseg[1];
        h0 = H0.x; h1 = H0.y; h2 = H0.z; h3 = H0.w;
        h4 = H1.x; h5 = H1.y; h6 = H1.z; h7 = H1.w;
    }

    if (lane < 8) {
        const size_t outs_sz = (size_t)T_SEQ * BATCH * NQ;
        float hmy = (wire==0)?h0:(wire==1)?h1:(wire==2)?h2:(wire==3)?h3:
                    (wire==4)?h4:(wire==5)?h5:(wire==6)?h6:h7;
        out[outs_sz + (size_t)row * NQ + wire] = hmy;                          // final hx
        out[outs_sz + (size_t)BATCH * NQ + (size_t)row * NQ + wire] = cstate;  // final cx
    }
}

// ---------------------------------------------------------------------------
// Launch
// ---------------------------------------------------------------------------
extern "C" void kernel_launch(void* const* d_in, const int* in_sizes, int n_in,
                              void* d_out, int out_size)
{
    const float* x   = (const float*)d_in[0];
    const float* Wf  = (const float*)d_in[1];
    const float* bf  = (const float*)d_in[2];
    const float* thf = (const float*)d_in[3];
    const float* Wi  = (const float*)d_in[4];
    const float* bi  = (const float*)d_in[5];
    const float* thi = (const float*)d_in[6];
    const float* Wu  = (const float*)d_in[7];
    const float* bu  = (const float*)d_in[8];
    const float* thu = (const float*)d_in[9];
    const float* Wo  = (const float*)d_in[10];
    const float* bo  = (const float*)d_in[11];
    const float* tho = (const float*)d_in[12];
    float* out = (float*)d_out;

    qlstm_gemm<<<(T_SEQ * BATCH) / 128, 128>>>(x, Wf, Wi, Wu, Wo);
    qlstm_recurrent<<<BATCH / 4, 128>>>(Wf, bf, thf, Wi, bi, thi,
                                        Wu, bu, thu, Wo, bo, tho, out);
}

// round 8
// speedup vs baseline: 2.0107x; 1.0182x over previous
#include <cuda_runtime.h>
#include <cstdint>

#define T_SEQ 128
#define BATCH 512
#define DIM   128
#define NQ    8
#define NCH   32   // 4 gates * 8 wires

typedef unsigned long long u64;

// Scratch: zpre[(t*BATCH+b)*32 + ch] = x_t[b] @ Wx[:,ch], ch = gate*8+wire
__device__ float g_zpre[(size_t)T_SEQ * BATCH * NCH];
// dump target for lanes that don't own an output slot (never read)
__device__ float g_dump[64];

__device__ __forceinline__ float tanh_approx(float x) {
    float r;
    asm("tanh.approx.f32 %0, %1;" : "=f"(r) : "f"(x));
    return r;
}
__device__ __forceinline__ void ffma2(u64& acc, u64 a, u64 b) {
    asm("fma.rn.f32x2 %0, %1, %2, %0;" : "+l"(acc) : "l"(a), "l"(b));
}
__device__ __forceinline__ u64 pack2(float lo, float hi) {
    u64 r; asm("mov.b64 %0, {%1, %2};" : "=l"(r) : "f"(lo), "f"(hi)); return r;
}

// ---------------------------------------------------------------------------
// Kernel A (proven, ~7us): zpre = X @ Wx via packed f32x2 FMA.
// ---------------------------------------------------------------------------
__global__ void __launch_bounds__(128) qlstm_gemm(
    const float* __restrict__ x,
    const float* __restrict__ Wf, const float* __restrict__ Wi,
    const float* __restrict__ Wu, const float* __restrict__ Wo)
{
    __shared__ __align__(16) float ws[128][32];
    __shared__ float xs[32][129];
    const int tid  = threadIdx.x;
    const int row0 = blockIdx.x * 128;

    #pragma unroll 4
    for (int i = tid; i < 128 * 32; i += 128) {
        int k = i >> 5, j = i & 31;
        int g = j >> 3, w = j & 7;
        const float* Wg = (g == 0) ? Wf : (g == 1) ? Wi : (g == 2) ? Wu : Wo;
        ws[k][j] = Wg[k * 8 + w];
    }

    const int lane = tid & 31;
    const int c0   = (tid >> 5) * 8;

    u64 acc[4][4];
    #pragma unroll
    for (int r = 0; r < 4; r++)
        #pragma unroll
        for (int q = 0; q < 4; q++) acc[r][q] = 0ull;

    for (int kc = 0; kc < 4; ++kc) {
        __syncthreads();
        #pragma unroll 4
        for (int i = tid; i < 128 * 32; i += 128) {
            int r = i >> 5, kk = i & 31;
            xs[kk][r] = x[(size_t)(row0 + r) * DIM + kc * 32 + kk];
        }
        __syncthreads();

        #pragma unroll
        for (int k = 0; k < 32; ++k) {
            float xv0 = xs[k][lane      ];
            float xv1 = xs[k][lane + 32 ];
            float xv2 = xs[k][lane + 64 ];
            float xv3 = xs[k][lane + 96 ];
            u64 xx0 = pack2(xv0, xv0);
            u64 xx1 = pack2(xv1, xv1);
            u64 xx2 = pack2(xv2, xv2);
            u64 xx3 = pack2(xv3, xv3);
            const u64* wk = reinterpret_cast<const u64*>(&ws[kc * 32 + k][c0]);
            u64 w0 = wk[0], w1 = wk[1], w2 = wk[2], w3 = wk[3];
            ffma2(acc[0][0], xx0, w0); ffma2(acc[0][1], xx0, w1);
            ffma2(acc[0][2], xx0, w2); ffma2(acc[0][3], xx0, w3);
            ffma2(acc[1][0], xx1, w0); ffma2(acc[1][1], xx1, w1);
            ffma2(acc[1][2], xx1, w2); ffma2(acc[1][3], xx1, w3);
            ffma2(acc[2][0], xx2, w0); ffma2(acc[2][1], xx2, w1);
            ffma2(acc[2][2], xx2, w2); ffma2(acc[2][3], xx2, w3);
            ffma2(acc[3][0], xx3, w0); ffma2(acc[3][1], xx3, w1);
            ffma2(acc[3][2], xx3, w2); ffma2(acc[3][3], xx3, w3);
        }
    }

    #pragma unroll
    for (int rr = 0; rr < 4; ++rr) {
        int r = row0 + lane + 32 * rr;
        u64* dst = reinterpret_cast<u64*>(g_zpre + (size_t)r * NCH + c0);
        dst[0] = acc[rr][0]; dst[1] = acc[rr][1];
        dst[2] = acc[rr][2]; dst[3] = acc[rr][3];
    }
}

// ---------------------------------------------------------------------------
// Kernel B: recurrence, one warp per row; ZERO shfl in the loop.
// Cross-lane exchange via warp-synchronous smem (no __syncwarp): body is
// fully branch-free so the warp stays converged; same-warp STS -> LDS
// program order is honored by the in-order LSU pipe.
// lane = gate*8 + wire.
// <Z_w> = prod_{k<=w} cos(phi_k) (w>=1), <Z_0> = prod_{k=1..7} cos(phi_k).
// ---------------------------------------------------------------------------
__global__ void __launch_bounds__(128) qlstm_recurrent(
    const float* __restrict__ Wf, const float* __restrict__ bf, const float* __restrict__ thf,
    const float* __restrict__ Wi, const float* __restrict__ bi, const float* __restrict__ thi,
    const float* __restrict__ Wu, const float* __restrict__ bu, const float* __restrict__ thu,
    const float* __restrict__ Wo, const float* __restrict__ bo, const float* __restrict__ tho,
    float* __restrict__ out)
{
    __shared__ __align__(16) float cbuf[4][32];   // cosines, by lane
    __shared__ __align__(16) float abuf[4][32];   // acts, [wire*4 + gate]
    __shared__ __align__(16) float hbuf[4][32];   // h, by lane

    const int lane = threadIdx.x & 31;
    const int warp = threadIdx.x >> 5;
    const int row  = blockIdx.x * 4 + warp;       // 0..511
    const int gate = lane >> 3;
    const int wire = lane & 7;
    const int base = lane & 24;                    // gate*8

    const float* Wg = (gate == 0) ? Wf : (gate == 1) ? Wi : (gate == 2) ? Wu : Wo;
    const float* bg = (gate == 0) ? bf : (gate == 1) ? bi : (gate == 2) ? bu : bo;
    const float* tg = (gate == 0) ? thf : (gate == 1) ? thi : (gate == 2) ? thu : tho;

    float wh0 = Wg[(DIM + 0) * NQ + wire];
    float wh1 = Wg[(DIM + 1) * NQ + wire];
    float wh2 = Wg[(DIM + 2) * NQ + wire];
    float wh3 = Wg[(DIM + 3) * NQ + wire];
    float wh4 = Wg[(DIM + 4) * NQ + wire];
    float wh5 = Wg[(DIM + 5) * NQ + wire];
    float wh6 = Wg[(DIM + 6) * NQ + wire];
    float wh7 = Wg[(DIM + 7) * NQ + wire];

    const float cbias = bg[wire] + tg[wire];
    const bool  isU   = (gate == 2);
    const float aScl  = isU ? 1.0f : 0.5f;
    const float aMul  = isU ? 1.0f : 0.5f;
    const float aAdd  = isU ? 0.0f : 0.5f;

    const bool p0 = (wire & 1) != 0;
    const bool p1 = (wire & 2) != 0;
    const bool p2 = (wire & 4) != 0;

    float h0=0,h1=0,h2=0,h3=0,h4=0,h5=0,h6=0,h7=0;
    float cstate = 0.0f;

    // branch-free output pointer (keeps the warp converged)
    float* st = (lane < 8) ? (out + (size_t)row * NQ + wire) : (g_dump + lane);
    const size_t sstr = (lane < 8) ? (size_t)(BATCH * NQ) : 0;

    const float* zp = g_zpre + (size_t)row * NCH + lane;
    const size_t tstride = (size_t)BATCH * NCH;
    float zn0 = zp[0];
    float zn1 = zp[tstride];

    float* cw = &cbuf[warp][0];
    float* aw = &abuf[warp][0];
    float* hw_ = &hbuf[warp][0];
    const float4* cseg = reinterpret_cast<const float4*>(cw + base);
    const float4* hseg = reinterpret_cast<const float4*>(hw_ + base);
    const float4* aseg = reinterpret_cast<const float4*>(aw + wire * 4);

    #pragma unroll 1
    for (int t = 0; t < T_SEQ; ++t) {
        float zb = zn0 + cbias;
        zn0 = zn1;
        int t2 = (t + 2 < T_SEQ) ? (t + 2) : (T_SEQ - 1);
        zn1 = zp[(size_t)t2 * tstride];             // off-chain prefetch

        // z = zb + h . wh  (mul/add tree)
        float m0 = h0*wh0, m1 = h1*wh1, m2 = h2*wh2, m3 = h3*wh3;
        float m4 = h4*wh4, m5 = h5*wh5, m6 = h6*wh6, m7 = h7*wh7;
        float a01 = m0+m1, a23 = m2+m3, a45 = m4+m5, a67 = m6+m7;
        float z = ((a01+a23) + (a45+a67)) + zb;

        float c = __cosf(z);

        // --- exchange 1: cosines (warp-synchronous smem, no sync) ---
        cw[lane] = c;
        float4 A = cseg[0];
        float4 B = cseg[1];
        float cc0 = A.x, cc1 = A.y, cc2 = A.z, cc3 = A.w;
        float cc4 = B.x, cc5 = B.y, cc6 = B.z, cc7 = B.w;

        // prefix products (Sklansky) + wire-bit mux
        float m01 = cc0*cc1, m23 = cc2*cc3, m45 = cc4*cc5, m67 = cc6*cc7;
        float m0123 = m01*m23, m4567 = m45*m67;
        float P1 = m01;
        float P2 = m01*cc2;
        float P3 = m0123;
        float P4 = m0123*cc4;
        float P5 = m0123*m45;
        float P6 = m0123*(m45*cc6);
        float P7 = m0123*m4567;
        float E0 = (cc1*m23)*m4567;          // prod c1..c7

        float t0v = p0 ? P1 : E0;
        float t1v = p0 ? P3 : P2;
        float t2v = p0 ? P5 : P4;
        float t3v = p0 ? P7 : P6;
        float u0 = p1 ? t1v : t0v;
        float u1 = p1 ? t3v : t2v;
        float e  = p2 ? u1 : u0;             // <Z_wire>

        float act = fmaf(aMul, tanh_approx(e * aScl), aAdd);

        // --- exchange 2: gate values, transposed for one LDS.128 gather ---
        aw[wire * 4 + gate] = act;
        float4 G = aseg[0];                   // (f, i, u, o) for this wire

        cstate   = fmaf(G.x, cstate, G.y * G.z);
        float hv = G.w * tanh_approx(cstate);

        *st = hv;                             // branch-free store
        st += sstr;

        // --- exchange 3: new hidden state ---
        hw_[lane] = hv;                       // identical per wire across gates
        float4 H0 = hseg[0];
        float4 H1 = hseg[1];
        h0 = H0.x; h1 = H0.y; h2 = H0.z; h3 = H0.w;
        h4 = H1.x; h5 = H1.y; h6 = H1.z; h7 = H1.w;
    }

    if (lane < 8) {
        const size_t outs_sz = (size_t)T_SEQ * BATCH * NQ;
        float hmy = (wire==0)?h0:(wire==1)?h1:(wire==2)?h2:(wire==3)?h3:
                    (wire==4)?h4:(wire==5)?h5:(wire==6)?h6:h7;
        out[outs_sz + (size_t)row * NQ + wire] = hmy;                          // final hx
        out[outs_sz + (size_t)BATCH * NQ + (size_t)row * NQ + wire] = cstate;  // final cx
    }
}

// ---------------------------------------------------------------------------
// Launch
// ---------------------------------------------------------------------------
extern "C" void kernel_launch(void* const* d_in, const int* in_sizes, int n_in,
                              void* d_out, int out_size)
{
    const float* x   = (const float*)d_in[0];
    const float* Wf  = (const float*)d_in[1];
    const float* bf  = (const float*)d_in[2];
    const float* thf = (const float*)d_in[3];
    const float* Wi  = (const float*)d_in[4];
    const float* bi  = (const float*)d_in[5];
    const float* thi = (const float*)d_in[6];
    const float* Wu  = (const float*)d_in[7];
    const float* bu  = (const float*)d_in[8];
    const float* thu = (const float*)d_in[9];
    const float* Wo  = (const float*)d_in[10];
    const float* bo  = (const float*)d_in[11];
    const float* tho = (const float*)d_in[12];
    float* out = (float*)d_out;

    qlstm_gemm<<<(T_SEQ * BATCH) / 128, 128>>>(x, Wf, Wi, Wu, Wo);
    qlstm_recurrent<<<BATCH / 4, 128>>>(Wf, bf, thf, Wi, bi, thi,
                                        Wu, bu, thu, Wo, bo, tho, out);
}